// round 1
// baseline (speedup 1.0000x reference)
#include <cuda_runtime.h>
#include <math.h>

// ---------------------------------------------------------------------------
// EarthAttention3D  (Pangu-style 3D window attention)
//   B=1, WN=960 windows, P=144 tokens/window, DIM=192, HEADS=6, DH=32
//   window grid (MZ,MH,MW)=(4,16,15); window type wt = w / 15
// Pipeline:
//   1) qkv  = x @ w_qkv  (scale q)           [138240 x 576  x 192]
//   2) per (w,h): S = QK^T + bias + mask ; softmax ; O = S V
//   3) out  = O @ w_proj + b_proj            [138240 x 192  x 192]
// ---------------------------------------------------------------------------

#define WN      960
#define PT      144          // tokens per window
#define DIMC    192
#define HEADS   6
#define DH      32
#define QKVD    576
#define MROWS   (WN * PT)    // 138240
#define QSCALEV 0.17677669529663687f

// Scratch (static device globals: allowed; no allocation APIs used)
__device__ float g_qkv[(size_t)MROWS * QKVD];   // 318 MB
__device__ float g_att[(size_t)MROWS * DIMC];   // 106 MB

// ---------------------------------------------------------------------------
// Generic tiled SGEMM:  C[M,N] = A[M,192] * B[192,N]   (M=138240, N in {576,192})
// BM=BN=64, BK=16, 256 threads, 4x4 register tile per thread.
// ---------------------------------------------------------------------------
template<int N, bool QSCALE, bool ADD_BIAS>
__global__ __launch_bounds__(256)
void gemm192_kernel(const float* __restrict__ A,
                    const float* __restrict__ B,
                    const float* __restrict__ bias,
                    float* __restrict__ C)
{
    __shared__ float As[16][64];   // transposed: As[k][m]
    __shared__ float Bs[16][64];

    const int tid = threadIdx.x;
    const int tx = tid & 15;          // 0..15  -> 4 cols each
    const int ty = tid >> 4;          // 0..15  -> 4 rows each
    const int rowBlk = blockIdx.y * 64;
    const int colBlk = blockIdx.x * 64;

    // load mapping
    const int arow = tid >> 2;            // 0..63
    const int akq  = (tid & 3) * 4;       // k quad
    const int brow = tid >> 4;            // 0..15
    const int bcol = (tid & 15) * 4;      // 0..60

    float acc[4][4] = {};

    for (int k0 = 0; k0 < 192; k0 += 16) {
        float4 av = *(const float4*)&A[(size_t)(rowBlk + arow) * 192 + k0 + akq];
        As[akq + 0][arow] = av.x;
        As[akq + 1][arow] = av.y;
        As[akq + 2][arow] = av.z;
        As[akq + 3][arow] = av.w;
        *(float4*)&Bs[brow][bcol] =
            *(const float4*)&B[(size_t)(k0 + brow) * N + colBlk + bcol];
        __syncthreads();

        #pragma unroll
        for (int kk = 0; kk < 16; kk++) {
            const float4 a4 = *(const float4*)&As[kk][ty * 4];
            const float4 b4 = *(const float4*)&Bs[kk][tx * 4];
            const float a[4] = {a4.x, a4.y, a4.z, a4.w};
            const float b[4] = {b4.x, b4.y, b4.z, b4.w};
            #pragma unroll
            for (int i = 0; i < 4; i++)
                #pragma unroll
                for (int j = 0; j < 4; j++)
                    acc[i][j] = fmaf(a[i], b[j], acc[i][j]);
        }
        __syncthreads();
    }

    const int colBase = colBlk + tx * 4;
    const float scale = (QSCALE && colBase < 192) ? QSCALEV : 1.0f;
    float4 bv = make_float4(0.f, 0.f, 0.f, 0.f);
    if (ADD_BIAS) bv = *(const float4*)&bias[colBase];

    #pragma unroll
    for (int i = 0; i < 4; i++) {
        const int row = rowBlk + ty * 4 + i;
        float4 o;
        o.x = acc[i][0] * scale + bv.x;
        o.y = acc[i][1] * scale + bv.y;
        o.z = acc[i][2] * scale + bv.z;
        o.w = acc[i][3] * scale + bv.w;
        *(float4*)&C[(size_t)row * N + colBase] = o;
    }
}

// ---------------------------------------------------------------------------
// Attention kernel: one block per (window, head).
// smem: Qs[144*33] Ks[144*33] Vs[144*32] Ss[144*145]  = 139,968 bytes
// ---------------------------------------------------------------------------
#define SQK 33
#define SSD 145
#define ATT_SMEM ((PT*SQK*2 + PT*DH + PT*SSD) * 4)

__global__ __launch_bounds__(256)
void attn_kernel(const float* __restrict__ mask,
                 const float* __restrict__ bias_table)
{
    const int w = blockIdx.x;
    const int h = blockIdx.y;
    const int tid = threadIdx.x;

    extern __shared__ float sm[];
    float* Qs = sm;                   // [144][33]
    float* Ks = Qs + PT * SQK;        // [144][33]
    float* Vs = Ks + PT * SQK;        // [144][32]  (float4-aligned)
    float* Ss = Vs + PT * DH;         // [144][145]

    // ---- load Q,K,V for this (w,h) --------------------------------------
    const float* qkvBase = g_qkv + (size_t)w * PT * QKVD + h * DH;
    for (int idx = tid; idx < PT * 8 * 3; idx += 256) {
        const int sel = idx / (PT * 8);
        const int rem = idx - sel * (PT * 8);
        const int p = rem >> 3;
        const int f = (rem & 7) * 4;
        float4 v = *(const float4*)&qkvBase[(size_t)p * QKVD + sel * DIMC + f];
        if (sel == 0) {
            Qs[p*SQK + f + 0] = v.x; Qs[p*SQK + f + 1] = v.y;
            Qs[p*SQK + f + 2] = v.z; Qs[p*SQK + f + 3] = v.w;
        } else if (sel == 1) {
            Ks[p*SQK + f + 0] = v.x; Ks[p*SQK + f + 1] = v.y;
            Ks[p*SQK + f + 2] = v.z; Ks[p*SQK + f + 3] = v.w;
        } else {
            *(float4*)&Vs[p*DH + f] = v;
        }
    }
    __syncthreads();

    // ---- S = Q K^T  (16x16 threads, 9x9 register tile) ------------------
    const int tx = tid & 15;
    const int ty = tid >> 4;
    float acc[9][9];
    #pragma unroll
    for (int r = 0; r < 9; r++)
        #pragma unroll
        for (int c = 0; c < 9; c++) acc[r][c] = 0.f;

    #pragma unroll 2
    for (int d = 0; d < DH; d++) {
        float qa[9], kb[9];
        #pragma unroll
        for (int r = 0; r < 9; r++) qa[r] = Qs[(ty + 16*r) * SQK + d];
        #pragma unroll
        for (int c = 0; c < 9; c++) kb[c] = Ks[(tx + 16*c) * SQK + d];
        #pragma unroll
        for (int r = 0; r < 9; r++)
            #pragma unroll
            for (int c = 0; c < 9; c++)
                acc[r][c] = fmaf(qa[r], kb[c], acc[r][c]);
    }

    // ---- add earth bias + mask, stash in smem ---------------------------
    // bias idx = (zi+2*zj)*828 + (hi+6*hj)*23 + (wi-wj+11)
    const int wtH = (w / 15) * HEADS + h;
    int ai[9], bj[9];
    #pragma unroll
    for (int r = 0; r < 9; r++) {
        const int i = ty + 16*r;
        const int zi = i / 72, hi = (i % 72) / 12, wi = i % 12;
        ai[r] = zi * 828 + hi * 23 + wi + 11;
    }
    #pragma unroll
    for (int c = 0; c < 9; c++) {
        const int j = tx + 16*c;
        const int zj = j / 72, hj = (j % 72) / 12, wj = j % 12;
        bj[c] = zj * 1656 + hj * 138 - wj;
    }
    const float* mrow = mask + (size_t)w * PT * PT;
    #pragma unroll
    for (int r = 0; r < 9; r++) {
        const int i = ty + 16*r;
        #pragma unroll
        for (int c = 0; c < 9; c++) {
            const int j = tx + 16*c;
            const float b = __ldg(&bias_table[(size_t)(ai[r] + bj[c]) * 384 + wtH]);
            Ss[i * SSD + j] = acc[r][c] + b + mrow[i * PT + j];
        }
    }
    __syncthreads();

    // ---- row softmax (8 warps x 18 rows) --------------------------------
    const int warp = tid >> 5;
    const int lane = tid & 31;
    for (int rr = 0; rr < 18; rr++) {
        const int i = warp * 18 + rr;
        float v[5];
        #pragma unroll
        for (int t = 0; t < 5; t++) {
            const int j = lane + 32 * t;
            v[t] = (j < PT) ? Ss[i * SSD + j] : -1e30f;
        }
        float m = v[0];
        #pragma unroll
        for (int t = 1; t < 5; t++) m = fmaxf(m, v[t]);
        #pragma unroll
        for (int off = 16; off > 0; off >>= 1)
            m = fmaxf(m, __shfl_xor_sync(0xffffffffu, m, off));
        float e[5], s = 0.f;
        #pragma unroll
        for (int t = 0; t < 5; t++) {
            const int j = lane + 32 * t;
            e[t] = (j < PT) ? __expf(v[t] - m) : 0.f;
            s += e[t];
        }
        #pragma unroll
        for (int off = 16; off > 0; off >>= 1)
            s += __shfl_xor_sync(0xffffffffu, s, off);
        const float inv = 1.f / s;
        #pragma unroll
        for (int t = 0; t < 5; t++) {
            const int j = lane + 32 * t;
            if (j < PT) Ss[i * SSD + j] = e[t] * inv;
        }
    }
    __syncthreads();

    // ---- O = S V  (128 threads: 8 d-quads x 16 row-groups, 9 rows each) -
    if (tid < 128) {
        const int otx = tid & 7;     // d quad
        const int oty = tid >> 3;    // 0..15
        const int d4 = otx * 4;
        float4 oacc[9];
        #pragma unroll
        for (int r = 0; r < 9; r++) oacc[r] = make_float4(0.f, 0.f, 0.f, 0.f);

        for (int j = 0; j < PT; j++) {
            const float4 vv = *(const float4*)&Vs[j * DH + d4];
            #pragma unroll
            for (int r = 0; r < 9; r++) {
                const float s = Ss[(oty + 16*r) * SSD + j];
                oacc[r].x = fmaf(s, vv.x, oacc[r].x);
                oacc[r].y = fmaf(s, vv.y, oacc[r].y);
                oacc[r].z = fmaf(s, vv.z, oacc[r].z);
                oacc[r].w = fmaf(s, vv.w, oacc[r].w);
            }
        }
        float* outp = g_att + (size_t)w * PT * DIMC + h * DH + d4;
        #pragma unroll
        for (int r = 0; r < 9; r++) {
            const int i = oty + 16*r;
            *(float4*)&outp[(size_t)i * DIMC] = oacc[r];
        }
    }
}

// ---------------------------------------------------------------------------
extern "C" void kernel_launch(void* const* d_in, const int* in_sizes, int n_in,
                              void* d_out, int out_size)
{
    const float* x          = (const float*)d_in[0];
    const float* mask       = (const float*)d_in[1];
    const float* w_qkv      = (const float*)d_in[2];
    const float* w_proj     = (const float*)d_in[3];
    const float* b_proj     = (const float*)d_in[4];
    const float* bias_table = (const float*)d_in[5];
    float* out = (float*)d_out;

    void* qkv_ptr = nullptr;
    void* att_ptr = nullptr;
    cudaGetSymbolAddress(&qkv_ptr, g_qkv);
    cudaGetSymbolAddress(&att_ptr, g_att);

    cudaFuncSetAttribute(attn_kernel,
                         cudaFuncAttributeMaxDynamicSharedMemorySize, ATT_SMEM);

    // 1) QKV projection (q scaled)
    gemm192_kernel<QKVD, true, false>
        <<<dim3(QKVD / 64, MROWS / 64), 256>>>(x, w_qkv, nullptr, (float*)qkv_ptr);

    // 2) windowed attention with earth bias + mask
    attn_kernel<<<dim3(WN, HEADS), 256, ATT_SMEM>>>(mask, bias_table);

    // 3) output projection + bias
    gemm192_kernel<DIMC, false, true>
        <<<dim3(DIMC / 64, MROWS / 64), 256>>>((const float*)att_ptr, w_proj,
                                               b_proj, out);
}

// round 4
// speedup vs baseline: 1.6048x; 1.6048x over previous
#include <cuda_runtime.h>
#include <cuda_fp16.h>

// ---------------------------------------------------------------------------
// EarthAttention3D — tensor-core (mma.sync f16.f32) pipeline
//   1) qkv = x @ w_qkv (3-term fp16 split GEMM, q pre-scaled, half output)
//   2) bias_pre: materialize earth bias -> g_bias[wt][h][144][144] (half)
//   3) attn: per (w,h) block, FA-style: S=QK^T (mma) +bias+mask, reg softmax
//            (FFMA exp), O=S V (mma) -> g_att fp32
//   4) out = g_att @ w_proj + b_proj (3-term split GEMM, fp32 output)
// ---------------------------------------------------------------------------

#define WN      960
#define PT      144
#define DIMC    192
#define HEADS   6
#define DH      32
#define QKVD    576
#define MROWS   (WN * PT)          // 138240
#define QSCALEV 0.17677669529663687f

__device__ __half g_qkvh[(size_t)MROWS * QKVD];   // 159 MB
__device__ float  g_att [(size_t)MROWS * DIMC];   // 106 MB
__device__ __half g_bias[(size_t)384 * PT * PT];  // 15.9 MB (L2-resident)

// ---------------------------------------------------------------------------
__device__ __forceinline__ void mma16816(float d[4], const unsigned a[4],
                                         const unsigned b[2], const float c[4])
{
    asm volatile(
        "mma.sync.aligned.m16n8k16.row.col.f32.f16.f16.f32 "
        "{%0,%1,%2,%3}, {%4,%5,%6,%7}, {%8,%9}, {%10,%11,%12,%13};\n"
        : "=f"(d[0]), "=f"(d[1]), "=f"(d[2]), "=f"(d[3])
        : "r"(a[0]), "r"(a[1]), "r"(a[2]), "r"(a[3]),
          "r"(b[0]), "r"(b[1]),
          "f"(c[0]), "f"(c[1]), "f"(c[2]), "f"(c[3]));
}

// FFMA-only exp (no MUFU): e^x = 2^n * 2^f, f in [-0.5,0.5], deg-5 poly.
__device__ __forceinline__ float fexp(float x)
{
    float t = x * 1.4426950408889634f;
    float n = rintf(t);
    float f = t - n;
    float p = 1.33333642e-3f;
    p = fmaf(p, f, 9.61812910e-3f);
    p = fmaf(p, f, 5.55041087e-2f);
    p = fmaf(p, f, 2.40226507e-1f);
    p = fmaf(p, f, 6.93147181e-1f);
    p = fmaf(p, f, 1.0f);
    int e = (int)n;
    e = max(e, -120);                        // x <= 0 here; guard underflow
    return __int_as_float((e + 127) << 23) * p;
}

// ---------------------------------------------------------------------------
// 3-term split fp16 GEMM:  C[M,N] = A[M,192]*B[192,N]  (fp32-class accuracy)
// block 256 thr (8 warps, 4x2), tile 128x64, k-chunk 16.
// ---------------------------------------------------------------------------
template<int N, bool OUT_HALF, bool QSCALE, bool ADDB>
__global__ __launch_bounds__(256)
void hgemm(const float* __restrict__ A, const float* __restrict__ B,
           const float* __restrict__ bias, void* __restrict__ Cout)
{
    __shared__ __half Ahi[128][24], Alo[128][24];   // stride 24 halves: conflict-free
    __shared__ __half Bhi[64][24],  Blo[64][24];    // stored [n][k]

    const int tid  = threadIdx.x;
    const int warp = tid >> 5, lane = tid & 31;
    const int wm = warp >> 1, wn = warp & 1;
    const int g  = lane >> 2, c2 = (lane & 3) * 2;
    const int rowBlk = blockIdx.y * 128, colBlk = blockIdx.x * 64;

    const int arow = tid >> 1, ak = (tid & 1) * 8;
    const int bk   = tid >> 4, bn = (tid & 15) * 4;

    float acc[2][4][4] = {};

    for (int k0 = 0; k0 < 192; k0 += 16) {
        // stage A chunk (128x16) as hi/lo halves
        const float* ap = A + (size_t)(rowBlk + arow) * 192 + k0 + ak;
        float4 v0 = *(const float4*)ap;
        float4 v1 = *(const float4*)(ap + 4);
        float va[8] = {v0.x, v0.y, v0.z, v0.w, v1.x, v1.y, v1.z, v1.w};
        #pragma unroll
        for (int i = 0; i < 8; i++) {
            __half hh = __float2half_rn(va[i]);
            Ahi[arow][ak + i] = hh;
            Alo[arow][ak + i] = __float2half_rn(va[i] - __half2float(hh));
        }
        // stage B chunk (16x64), transposed to [n][k]
        const float* bp = B + (size_t)(k0 + bk) * N + colBlk + bn;
        float4 vb = *(const float4*)bp;
        float vbb[4] = {vb.x, vb.y, vb.z, vb.w};
        #pragma unroll
        for (int i = 0; i < 4; i++) {
            __half hh = __float2half_rn(vbb[i]);
            Bhi[bn + i][bk] = hh;
            Blo[bn + i][bk] = __float2half_rn(vbb[i] - __half2float(hh));
        }
        __syncthreads();

        unsigned ah[2][4], al[2][4];
        #pragma unroll
        for (int m = 0; m < 2; m++) {
            const int r = wm * 32 + m * 16;
            ah[m][0] = *(const unsigned*)&Ahi[r + g    ][c2    ];
            ah[m][1] = *(const unsigned*)&Ahi[r + g + 8][c2    ];
            ah[m][2] = *(const unsigned*)&Ahi[r + g    ][c2 + 8];
            ah[m][3] = *(const unsigned*)&Ahi[r + g + 8][c2 + 8];
            al[m][0] = *(const unsigned*)&Alo[r + g    ][c2    ];
            al[m][1] = *(const unsigned*)&Alo[r + g + 8][c2    ];
            al[m][2] = *(const unsigned*)&Alo[r + g    ][c2 + 8];
            al[m][3] = *(const unsigned*)&Alo[r + g + 8][c2 + 8];
        }
        #pragma unroll
        for (int n = 0; n < 4; n++) {
            const int nrow = wn * 32 + n * 8 + g;
            unsigned bh[2], bl[2];
            bh[0] = *(const unsigned*)&Bhi[nrow][c2    ];
            bh[1] = *(const unsigned*)&Bhi[nrow][c2 + 8];
            bl[0] = *(const unsigned*)&Blo[nrow][c2    ];
            bl[1] = *(const unsigned*)&Blo[nrow][c2 + 8];
            #pragma unroll
            for (int m = 0; m < 2; m++) {
                mma16816(acc[m][n], ah[m], bh, acc[m][n]);
                mma16816(acc[m][n], al[m], bh, acc[m][n]);
                mma16816(acc[m][n], ah[m], bl, acc[m][n]);
            }
        }
        __syncthreads();
    }

    #pragma unroll
    for (int m = 0; m < 2; m++) {
        const int row0 = rowBlk + wm * 32 + m * 16 + g;
        #pragma unroll
        for (int n = 0; n < 4; n++) {
            const int col = colBlk + wn * 32 + n * 8 + c2;
            if (OUT_HALF) {
                const float s = (QSCALE && col < DIMC) ? QSCALEV : 1.0f;
                __half* o = (__half*)Cout;
                __half2 h0 = __floats2half2_rn(acc[m][n][0] * s, acc[m][n][1] * s);
                __half2 h1 = __floats2half2_rn(acc[m][n][2] * s, acc[m][n][3] * s);
                *(__half2*)&o[(size_t)row0 * N + col]       = h0;
                *(__half2*)&o[(size_t)(row0 + 8) * N + col] = h1;
            } else {
                float bx = 0.f, by = 0.f;
                if (ADDB) { float2 bv = *(const float2*)&bias[col]; bx = bv.x; by = bv.y; }
                float* o = (float*)Cout;
                *(float2*)&o[(size_t)row0 * N + col] =
                    make_float2(acc[m][n][0] + bx, acc[m][n][1] + by);
                *(float2*)&o[(size_t)(row0 + 8) * N + col] =
                    make_float2(acc[m][n][2] + bx, acc[m][n][3] + by);
            }
        }
    }
}

// ---------------------------------------------------------------------------
// Materialize earth bias: g_bias[(wt*6+h)][i][j]  (half)
// idx = (zi+2*zj)*828 + (hi+6*hj)*23 + (wi-wj+11);  table[idx*384 + wt*6+h]
// ---------------------------------------------------------------------------
__global__ __launch_bounds__(256)
void bias_pre(const float* __restrict__ table)
{
    const int wh = blockIdx.x;                    // wt*6 + h, 0..383
    __half* out = g_bias + (size_t)wh * PT * PT;
    for (int t = threadIdx.x; t < PT * PT; t += 256) {
        const int i = t / PT, j = t % PT;
        const int zi = i / 72, hi = (i % 72) / 12, wi = i % 12;
        const int zj = j / 72, hj = (j % 72) / 12, wj = j % 12;
        const int idx = (zi + 2 * zj) * 828 + (hi + 6 * hj) * 23 + (wi - wj + 11);
        out[t] = __float2half_rn(__ldg(&table[(size_t)idx * 384 + wh]));
    }
}

// ---------------------------------------------------------------------------
// Attention: one block per (w,h); 9 warps, warp = 16-row strip.
// S in registers; fp16 mma for QK^T and SV; FFMA softmax.
// ---------------------------------------------------------------------------
__global__ __launch_bounds__(288)
void attn_kernel(const float* __restrict__ mask)
{
    __shared__ __half Qh[PT][40], Kh[PT][40];     // stride 40 halves: conflict-free
    __shared__ __half Vt[DH][152];                // transposed V: [d][token]

    const int w = blockIdx.x, h = blockIdx.y;
    const int tid = threadIdx.x;
    const int warp = tid >> 5, lane = tid & 31;
    const int g = lane >> 2, c2 = (lane & 3) * 2;

    // ---- stage Q,K,V (already half, q pre-scaled) -----------------------
    const __half* qkv = g_qkvh + (size_t)w * PT * QKVD + h * DH;
    for (int t = tid; t < 3 * 576; t += 288) {
        const int sel = t / 576, r = t % 576;
        const int p = r >> 2, grp = (r & 3) * 8;
        uint4 v = *(const uint4*)&qkv[(size_t)p * QKVD + sel * DIMC + grp];
        if (sel == 0)      *(uint4*)&Qh[p][grp] = v;
        else if (sel == 1) *(uint4*)&Kh[p][grp] = v;
        else {
            const __half* hv = (const __half*)&v;
            #pragma unroll
            for (int i = 0; i < 8; i++) Vt[grp + i][p] = hv[i];
        }
    }
    __syncthreads();

    // ---- S = Q K^T ------------------------------------------------------
    const int mrow = warp * 16;
    unsigned aq[2][4];
    #pragma unroll
    for (int ks = 0; ks < 2; ks++) {
        const int k0 = ks * 16;
        aq[ks][0] = *(const unsigned*)&Qh[mrow + g    ][k0 + c2    ];
        aq[ks][1] = *(const unsigned*)&Qh[mrow + g + 8][k0 + c2    ];
        aq[ks][2] = *(const unsigned*)&Qh[mrow + g    ][k0 + c2 + 8];
        aq[ks][3] = *(const unsigned*)&Qh[mrow + g + 8][k0 + c2 + 8];
    }
    float S[18][4];
    #pragma unroll
    for (int j = 0; j < 18; j++) { S[j][0] = S[j][1] = S[j][2] = S[j][3] = 0.f; }
    #pragma unroll
    for (int j = 0; j < 18; j++) {
        unsigned b[2];
        b[0] = *(const unsigned*)&Kh[j * 8 + g][c2    ];
        b[1] = *(const unsigned*)&Kh[j * 8 + g][c2 + 8];
        mma16816(S[j], aq[0], b, S[j]);
        b[0] = *(const unsigned*)&Kh[j * 8 + g][16 + c2    ];
        b[1] = *(const unsigned*)&Kh[j * 8 + g][16 + c2 + 8];
        mma16816(S[j], aq[1], b, S[j]);
    }

    // ---- + bias + mask --------------------------------------------------
    const int r0 = mrow + g, r1 = r0 + 8;
    const __half* bb = g_bias + (size_t)((w / 15) * HEADS + h) * PT * PT;
    const float*  mm = mask + (size_t)w * PT * PT;
    #pragma unroll
    for (int j = 0; j < 18; j++) {
        const int col = j * 8 + c2;
        const __half2 b0 = *(const __half2*)&bb[r0 * PT + col];
        const __half2 b1 = *(const __half2*)&bb[r1 * PT + col];
        const float2  m0 = *(const float2*)&mm[r0 * PT + col];
        const float2  m1 = *(const float2*)&mm[r1 * PT + col];
        S[j][0] += __low2float(b0)  + m0.x;
        S[j][1] += __high2float(b0) + m0.y;
        S[j][2] += __low2float(b1)  + m1.x;
        S[j][3] += __high2float(b1) + m1.y;
    }

    // ---- softmax (rows r0, r1 live across quad lanes) -------------------
    float mx0 = -1e30f, mx1 = -1e30f;
    #pragma unroll
    for (int j = 0; j < 18; j++) {
        mx0 = fmaxf(mx0, fmaxf(S[j][0], S[j][1]));
        mx1 = fmaxf(mx1, fmaxf(S[j][2], S[j][3]));
    }
    #pragma unroll
    for (int off = 1; off <= 2; off <<= 1) {
        mx0 = fmaxf(mx0, __shfl_xor_sync(0xffffffffu, mx0, off));
        mx1 = fmaxf(mx1, __shfl_xor_sync(0xffffffffu, mx1, off));
    }
    float s0 = 0.f, s1 = 0.f;
    #pragma unroll
    for (int j = 0; j < 18; j++) {
        S[j][0] = fexp(S[j][0] - mx0);  s0 += S[j][0];
        S[j][1] = fexp(S[j][1] - mx0);  s0 += S[j][1];
        S[j][2] = fexp(S[j][2] - mx1);  s1 += S[j][2];
        S[j][3] = fexp(S[j][3] - mx1);  s1 += S[j][3];
    }
    #pragma unroll
    for (int off = 1; off <= 2; off <<= 1) {
        s0 += __shfl_xor_sync(0xffffffffu, s0, off);
        s1 += __shfl_xor_sync(0xffffffffu, s1, off);
    }
    const float i0 = 1.f / s0, i1 = 1.f / s1;
    unsigned p0[18], p1[18];
    #pragma unroll
    for (int j = 0; j < 18; j++) {
        __half2 h0 = __floats2half2_rn(S[j][0] * i0, S[j][1] * i0);
        __half2 h1 = __floats2half2_rn(S[j][2] * i1, S[j][3] * i1);
        p0[j] = *(unsigned*)&h0;
        p1[j] = *(unsigned*)&h1;
    }

    // ---- O = P V --------------------------------------------------------
    float O[4][4] = {};
    #pragma unroll
    for (int t = 0; t < 9; t++) {
        const unsigned a[4] = {p0[2 * t], p1[2 * t], p0[2 * t + 1], p1[2 * t + 1]};
        #pragma unroll
        for (int n = 0; n < 4; n++) {
            unsigned b[2];
            b[0] = *(const unsigned*)&Vt[n * 8 + g][t * 16 + c2    ];
            b[1] = *(const unsigned*)&Vt[n * 8 + g][t * 16 + c2 + 8];
            mma16816(O[n], a, b, O[n]);
        }
    }
    float* op = g_att + (size_t)w * PT * DIMC + h * DH;
    #pragma unroll
    for (int n = 0; n < 4; n++) {
        const int col = n * 8 + c2;
        *(float2*)&op[(size_t)r0 * DIMC + col] = make_float2(O[n][0], O[n][1]);
        *(float2*)&op[(size_t)r1 * DIMC + col] = make_float2(O[n][2], O[n][3]);
    }
}

// ---------------------------------------------------------------------------
extern "C" void kernel_launch(void* const* d_in, const int* in_sizes, int n_in,
                              void* d_out, int out_size)
{
    const float* x          = (const float*)d_in[0];
    const float* mask       = (const float*)d_in[1];
    const float* w_qkv      = (const float*)d_in[2];
    const float* w_proj     = (const float*)d_in[3];
    const float* b_proj     = (const float*)d_in[4];
    const float* bias_table = (const float*)d_in[5];
    float* out = (float*)d_out;

    void* qkv_ptr = nullptr;
    void* att_ptr = nullptr;
    cudaGetSymbolAddress(&qkv_ptr, g_qkvh);
    cudaGetSymbolAddress(&att_ptr, g_att);

    // 1) QKV projection (3-term split, q scaled, half output)
    hgemm<QKVD, true, true, false>
        <<<dim3(QKVD / 64, MROWS / 128), 256>>>(x, w_qkv, nullptr, qkv_ptr);

    // 2) earth-bias materialization (independent of 1)
    bias_pre<<<384, 256>>>(bias_table);

    // 3) windowed attention
    attn_kernel<<<dim3(WN, HEADS), 288>>>(mask);

    // 4) output projection (3-term split, fp32 + bias)
    hgemm<DIMC, false, false, true>
        <<<dim3(DIMC / 64, MROWS / 128), 256>>>((const float*)att_ptr, w_proj,
                                                b_proj, out);
}

// round 7
// speedup vs baseline: 2.5643x; 1.5979x over previous
#include <cuda_runtime.h>
#include <cuda_fp16.h>
#include <cstdint>
#include <stdint.h>

// ---------------------------------------------------------------------------
// EarthAttention3D — mma.sync f16 pipeline, ldmatrix + cp.async GEMMs
// ---------------------------------------------------------------------------

#define WN      960
#define PT      144
#define DIMC    192
#define HEADS   6
#define DH      32
#define QKVD    576
#define MROWS   (WN * PT)          // 138240
#define QSCALEV 0.17677669529663687f

__device__ __half g_qkvh[(size_t)MROWS * QKVD];   // 159 MB
__device__ float  g_att [(size_t)MROWS * DIMC];   // 106 MB
__device__ __half g_bias[(size_t)384 * PT * PT];  // 15.9 MB (L2-resident)
__device__ __half g_wqhi[192 * QKVD], g_wqlo[192 * QKVD];
__device__ __half g_wphi[192 * DIMC], g_wplo[192 * DIMC];

// ---------------------------------------------------------------------------
__device__ __forceinline__ void mma16816(float d[4], const unsigned a[4],
                                         const unsigned b0, const unsigned b1)
{
    asm volatile(
        "mma.sync.aligned.m16n8k16.row.col.f32.f16.f16.f32 "
        "{%0,%1,%2,%3}, {%4,%5,%6,%7}, {%8,%9}, {%0,%1,%2,%3};\n"
        : "+f"(d[0]), "+f"(d[1]), "+f"(d[2]), "+f"(d[3])
        : "r"(a[0]), "r"(a[1]), "r"(a[2]), "r"(a[3]), "r"(b0), "r"(b1));
}
__device__ __forceinline__ void ldmx4(unsigned r[4], unsigned addr)
{
    asm volatile("ldmatrix.sync.aligned.m8n8.x4.shared.b16 {%0,%1,%2,%3}, [%4];"
                 : "=r"(r[0]), "=r"(r[1]), "=r"(r[2]), "=r"(r[3]) : "r"(addr));
}
__device__ __forceinline__ void ldmx4t(unsigned r[4], unsigned addr)
{
    asm volatile("ldmatrix.sync.aligned.m8n8.x4.trans.shared.b16 {%0,%1,%2,%3}, [%4];"
                 : "=r"(r[0]), "=r"(r[1]), "=r"(r[2]), "=r"(r[3]) : "r"(addr));
}
__device__ __forceinline__ void cpa16(unsigned s, const void* g)
{
    asm volatile("cp.async.ca.shared.global [%0], [%1], 16;\n" :: "r"(s), "l"(g));
}
__device__ __forceinline__ void cp_commit()
{
    asm volatile("cp.async.commit_group;\n");
}
template<int I> __device__ __forceinline__ void cp_wait()
{
    asm volatile("cp.async.wait_group %0;\n" :: "n"(I));
}

// FFMA-only exp
__device__ __forceinline__ float fexp(float x)
{
    float t = x * 1.4426950408889634f;
    float n = rintf(t);
    float f = t - n;
    float p = 1.33333642e-3f;
    p = fmaf(p, f, 9.61812910e-3f);
    p = fmaf(p, f, 5.55041087e-2f);
    p = fmaf(p, f, 2.40226507e-1f);
    p = fmaf(p, f, 6.93147181e-1f);
    p = fmaf(p, f, 1.0f);
    int e = (int)n;
    e = max(e, -120);
    return __int_as_float((e + 127) << 23) * p;
}

// ---------------------------------------------------------------------------
// weight split prep: w fp32 -> hi/lo half
__global__ void conv_w(const float* __restrict__ w, __half* __restrict__ hi,
                       __half* __restrict__ lo, int n)
{
    int i = blockIdx.x * 256 + threadIdx.x;
    if (i < n) {
        float v = w[i];
        __half h = __float2half_rn(v);
        hi[i] = h;
        lo[i] = __float2half_rn(v - __half2float(h));
    }
}

// ---------------------------------------------------------------------------
// hgemm3: C[M,N] = A[M,192] * B[192,N], 3-term fp16 split, fp32-class.
// Block = 128 rows x full N (chunks of 64). A staged once (hi+lo, full K).
// B (pre-split weights) streamed via cp.async double buffer.
// ---------------------------------------------------------------------------
#define AST 200                     // A smem stride (halves), 400B rows
#define BST 72                      // B smem stride (halves), 144B rows
#define HG_SMEM ((2 * 128 * AST + 2 * 64 * BST) * 2)   // 120,832 B

template<int N, bool OUT_HALF, bool QSCALE, bool ADDB>
__global__ __launch_bounds__(256, 1)
void hgemm3(const float* __restrict__ A, const __half* __restrict__ Bhi,
            const __half* __restrict__ Blo, const float* __restrict__ bias,
            void* __restrict__ Cout)
{
    extern __shared__ __half sm[];
    __half* Ahi = sm;                         // [128][AST]
    __half* Alo = Ahi + 128 * AST;            // [128][AST]
    __half* Bbuf = Alo + 128 * AST;           // 2 stages x (hi[32][BST], lo[32][BST])

    const int tid  = threadIdx.x;
    const int warp = tid >> 5, lane = tid & 31;
    const int wm = warp >> 1, wn = warp & 1;  // 4x2 warp grid
    const int g  = lane >> 2, c2 = (lane & 3) * 2;
    const int laneRow = lane & 15, laneCol = (lane >> 4) * 8;
    const int rowBlk = blockIdx.x * 128;

    const unsigned aHiAddr = (unsigned)__cvta_generic_to_shared(Ahi);
    const unsigned aLoOff  = 128 * AST * 2;   // bytes
    const unsigned bAddr   = (unsigned)__cvta_generic_to_shared(Bbuf);

    // ---- stage A (128 x 192) once, split hi/lo --------------------------
    for (int idx = tid; idx < 128 * 48; idx += 256) {
        const int row = idx / 48, f4 = idx % 48;
        float4 v = *(const float4*)&A[(size_t)(rowBlk + row) * 192 + f4 * 4];
        float va[4] = {v.x, v.y, v.z, v.w};
        __half hh[4], hl[4];
        #pragma unroll
        for (int i = 0; i < 4; i++) {
            hh[i] = __float2half_rn(va[i]);
            hl[i] = __float2half_rn(va[i] - __half2float(hh[i]));
        }
        *(uint2*)&Ahi[row * AST + f4 * 4] = *(uint2*)hh;
        *(uint2*)&Alo[row * AST + f4 * 4] = *(uint2*)hl;
    }

    const int br = tid >> 3, bseg = (tid & 7) * 8;   // 32 rows x 8x8 halves

    #pragma unroll 1
    for (int c0 = 0; c0 < N; c0 += 64) {
        // prologue: stage 0 <- k0=0
        {
            unsigned s = bAddr + (unsigned)(br * BST + bseg) * 2;
            cpa16(s,                  &Bhi[(size_t)br * N + c0 + bseg]);
            cpa16(s + 32 * BST * 2,   &Blo[(size_t)br * N + c0 + bseg]);
            cp_commit();
        }

        float acc[2][4][4] = {};

        #pragma unroll
        for (int ks = 0; ks < 6; ks++) {
            if (ks < 5) {
                const int kn = (ks + 1) * 32;
                unsigned s = bAddr + (unsigned)(((ks + 1) & 1) * 64 * BST
                                                + br * BST + bseg) * 2;
                cpa16(s,                &Bhi[(size_t)(kn + br) * N + c0 + bseg]);
                cpa16(s + 32 * BST * 2, &Blo[(size_t)(kn + br) * N + c0 + bseg]);
                cp_commit();
                cp_wait<1>();
            } else {
                cp_wait<0>();
            }
            __syncthreads();

            const int k0 = ks * 32;
            const unsigned bStage = bAddr + (unsigned)((ks & 1) * 64 * BST) * 2;

            unsigned ah[2][2][4], al[2][2][4];     // [t][m]
            #pragma unroll
            for (int t = 0; t < 2; t++)
                #pragma unroll
                for (int m = 0; m < 2; m++) {
                    unsigned ad = aHiAddr +
                        (unsigned)((wm * 32 + m * 16 + laneRow) * AST
                                   + k0 + t * 16 + laneCol) * 2;
                    ldmx4(ah[t][m], ad);
                    ldmx4(al[t][m], ad + aLoOff);
                }
            unsigned bh[2][2][4], bl[2][2][4];     // [t][p] p = n-pair
            #pragma unroll
            for (int t = 0; t < 2; t++)
                #pragma unroll
                for (int p = 0; p < 2; p++) {
                    unsigned bd = bStage +
                        (unsigned)((t * 16 + laneRow) * BST
                                   + wn * 32 + p * 16 + laneCol) * 2;
                    ldmx4t(bh[t][p], bd);
                    ldmx4t(bl[t][p], bd + 32 * BST * 2);
                }
            #pragma unroll
            for (int t = 0; t < 2; t++)
                #pragma unroll
                for (int m = 0; m < 2; m++)
                    #pragma unroll
                    for (int p = 0; p < 2; p++) {
                        mma16816(acc[m][2*p  ], ah[t][m], bh[t][p][0], bh[t][p][1]);
                        mma16816(acc[m][2*p  ], al[t][m], bh[t][p][0], bh[t][p][1]);
                        mma16816(acc[m][2*p  ], ah[t][m], bl[t][p][0], bl[t][p][1]);
                        mma16816(acc[m][2*p+1], ah[t][m], bh[t][p][2], bh[t][p][3]);
                        mma16816(acc[m][2*p+1], al[t][m], bh[t][p][2], bh[t][p][3]);
                        mma16816(acc[m][2*p+1], ah[t][m], bl[t][p][2], bl[t][p][3]);
                    }
            __syncthreads();
        }

        // ---- epilogue for this 64-col chunk -----------------------------
        #pragma unroll
        for (int m = 0; m < 2; m++) {
            const int row0 = rowBlk + wm * 32 + m * 16 + g;
            #pragma unroll
            for (int n = 0; n < 4; n++) {
                const int col = c0 + wn * 32 + n * 8 + c2;
                if (OUT_HALF) {
                    const float s = (QSCALE && col < DIMC) ? QSCALEV : 1.0f;
                    __half* o = (__half*)Cout;
                    __half2 h0 = __floats2half2_rn(acc[m][n][0] * s, acc[m][n][1] * s);
                    __half2 h1 = __floats2half2_rn(acc[m][n][2] * s, acc[m][n][3] * s);
                    *(__half2*)&o[(size_t)row0 * N + col]       = h0;
                    *(__half2*)&o[(size_t)(row0 + 8) * N + col] = h1;
                } else {
                    float bx = 0.f, by = 0.f;
                    if (ADDB) { float2 bv = *(const float2*)&bias[col]; bx = bv.x; by = bv.y; }
                    float* o = (float*)Cout;
                    *(float2*)&o[(size_t)row0 * N + col] =
                        make_float2(acc[m][n][0] + bx, acc[m][n][1] + by);
                    *(float2*)&o[(size_t)(row0 + 8) * N + col] =
                        make_float2(acc[m][n][2] + bx, acc[m][n][3] + by);
                }
            }
        }
    }
}

// ---------------------------------------------------------------------------
// earth-bias materialization
// ---------------------------------------------------------------------------
__global__ __launch_bounds__(256)
void bias_pre(const float* __restrict__ table)
{
    const int wh = blockIdx.x;                    // wt*6 + h
    __half* out = g_bias + (size_t)wh * PT * PT;
    for (int t = threadIdx.x; t < PT * PT; t += 256) {
        const int i = t / PT, j = t % PT;
        const int zi = i / 72, hi = (i % 72) / 12, wi = i % 12;
        const int zj = j / 72, hj = (j % 72) / 12, wj = j % 12;
        const int idx = (zi + 2 * zj) * 828 + (hi + 6 * hj) * 23 + (wi - wj + 11);
        out[t] = __float2half_rn(__ldg(&table[(size_t)idx * 384 + wh]));
    }
}

// ---------------------------------------------------------------------------
// Attention: one block per (w,h); 9 warps, warp = 16-row strip.
// ---------------------------------------------------------------------------
__global__ __launch_bounds__(288)
void attn_kernel(const float* __restrict__ mask)
{
    __shared__ __half Qh[PT][40], Kh[PT][40];
    __shared__ __half Vt[DH][152];

    const int w = blockIdx.x, h = blockIdx.y;
    const int tid = threadIdx.x;
    const int warp = tid >> 5, lane = tid & 31;
    const int g = lane >> 2, c2 = (lane & 3) * 2;

    const __half* qkv = g_qkvh + (size_t)w * PT * QKVD + h * DH;
    for (int t = tid; t < 3 * 576; t += 288) {
        const int sel = t / 576, r = t % 576;
        const int p = r >> 2, grp = (r & 3) * 8;
        uint4 v = *(const uint4*)&qkv[(size_t)p * QKVD + sel * DIMC + grp];
        if (sel == 0)      *(uint4*)&Qh[p][grp] = v;
        else if (sel == 1) *(uint4*)&Kh[p][grp] = v;
        else {
            const __half* hv = (const __half*)&v;
            #pragma unroll
            for (int i = 0; i < 8; i++) Vt[grp + i][p] = hv[i];
        }
    }
    __syncthreads();

    const int mrow = warp * 16;
    unsigned aq[2][4];
    #pragma unroll
    for (int ks = 0; ks < 2; ks++) {
        const int k0 = ks * 16;
        aq[ks][0] = *(const unsigned*)&Qh[mrow + g    ][k0 + c2    ];
        aq[ks][1] = *(const unsigned*)&Qh[mrow + g + 8][k0 + c2    ];
        aq[ks][2] = *(const unsigned*)&Qh[mrow + g    ][k0 + c2 + 8];
        aq[ks][3] = *(const unsigned*)&Qh[mrow + g + 8][k0 + c2 + 8];
    }
    float S[18][4];
    #pragma unroll
    for (int j = 0; j < 18; j++) { S[j][0] = S[j][1] = S[j][2] = S[j][3] = 0.f; }
    #pragma unroll
    for (int j = 0; j < 18; j++) {
        unsigned b0 = *(const unsigned*)&Kh[j * 8 + g][c2    ];
        unsigned b1 = *(const unsigned*)&Kh[j * 8 + g][c2 + 8];
        mma16816(S[j], aq[0], b0, b1);
        b0 = *(const unsigned*)&Kh[j * 8 + g][16 + c2    ];
        b1 = *(const unsigned*)&Kh[j * 8 + g][16 + c2 + 8];
        mma16816(S[j], aq[1], b0, b1);
    }

    const int r0 = mrow + g, r1 = r0 + 8;
    const __half* bb = g_bias + (size_t)((w / 15) * HEADS + h) * PT * PT;
    const float*  mm = mask + (size_t)w * PT * PT;
    #pragma unroll
    for (int j = 0; j < 18; j++) {
        const int col = j * 8 + c2;
        const __half2 b0 = *(const __half2*)&bb[r0 * PT + col];
        const __half2 b1 = *(const __half2*)&bb[r1 * PT + col];
        const float2  m0 = *(const float2*)&mm[r0 * PT + col];
        const float2  m1 = *(const float2*)&mm[r1 * PT + col];
        S[j][0] += __low2float(b0)  + m0.x;
        S[j][1] += __high2float(b0) + m0.y;
        S[j][2] += __low2float(b1)  + m1.x;
        S[j][3] += __high2float(b1) + m1.y;
    }

    float mx0 = -1e30f, mx1 = -1e30f;
    #pragma unroll
    for (int j = 0; j < 18; j++) {
        mx0 = fmaxf(mx0, fmaxf(S[j][0], S[j][1]));
        mx1 = fmaxf(mx1, fmaxf(S[j][2], S[j][3]));
    }
    #pragma unroll
    for (int off = 1; off <= 2; off <<= 1) {
        mx0 = fmaxf(mx0, __shfl_xor_sync(0xffffffffu, mx0, off));
        mx1 = fmaxf(mx1, __shfl_xor_sync(0xffffffffu, mx1, off));
    }
    float s0 = 0.f, s1 = 0.f;
    #pragma unroll
    for (int j = 0; j < 18; j++) {
        S[j][0] = fexp(S[j][0] - mx0);  s0 += S[j][0];
        S[j][1] = fexp(S[j][1] - mx0);  s0 += S[j][1];
        S[j][2] = fexp(S[j][2] - mx1);  s1 += S[j][2];
        S[j][3] = fexp(S[j][3] - mx1);  s1 += S[j][3];
    }
    #pragma unroll
    for (int off = 1; off <= 2; off <<= 1) {
        s0 += __shfl_xor_sync(0xffffffffu, s0, off);
        s1 += __shfl_xor_sync(0xffffffffu, s1, off);
    }
    const float i0 = 1.f / s0, i1 = 1.f / s1;
    unsigned p0[18], p1[18];
    #pragma unroll
    for (int j = 0; j < 18; j++) {
        __half2 h0 = __floats2half2_rn(S[j][0] * i0, S[j][1] * i0);
        __half2 h1 = __floats2half2_rn(S[j][2] * i1, S[j][3] * i1);
        p0[j] = *(unsigned*)&h0;
        p1[j] = *(unsigned*)&h1;
    }

    float O[4][4] = {};
    #pragma unroll
    for (int t = 0; t < 9; t++) {
        const unsigned a[4] = {p0[2 * t], p1[2 * t], p0[2 * t + 1], p1[2 * t + 1]};
        #pragma unroll
        for (int n = 0; n < 4; n++) {
            unsigned b0 = *(const unsigned*)&Vt[n * 8 + g][t * 16 + c2    ];
            unsigned b1 = *(const unsigned*)&Vt[n * 8 + g][t * 16 + c2 + 8];
            mma16816(O[n], a, b0, b1);
        }
    }
    float* op = g_att + (size_t)w * PT * DIMC + h * DH;
    #pragma unroll
    for (int n = 0; n < 4; n++) {
        const int col = n * 8 + c2;
        *(float2*)&op[(size_t)r0 * DIMC + col] = make_float2(O[n][0], O[n][1]);
        *(float2*)&op[(size_t)r1 * DIMC + col] = make_float2(O[n][2], O[n][3]);
    }
}

// ---------------------------------------------------------------------------
extern "C" void kernel_launch(void* const* d_in, const int* in_sizes, int n_in,
                              void* d_out, int out_size)
{
    const float* x          = (const float*)d_in[0];
    const float* mask       = (const float*)d_in[1];
    const float* w_qkv      = (const float*)d_in[2];
    const float* w_proj     = (const float*)d_in[3];
    const float* b_proj     = (const float*)d_in[4];
    const float* bias_table = (const float*)d_in[5];
    float* out = (float*)d_out;

    void *qkv_ptr = nullptr, *att_ptr = nullptr;
    void *wqh = nullptr, *wql = nullptr, *wph = nullptr, *wpl = nullptr;
    cudaGetSymbolAddress(&qkv_ptr, g_qkvh);
    cudaGetSymbolAddress(&att_ptr, g_att);
    cudaGetSymbolAddress(&wqh, g_wqhi);
    cudaGetSymbolAddress(&wql, g_wqlo);
    cudaGetSymbolAddress(&wph, g_wphi);
    cudaGetSymbolAddress(&wpl, g_wplo);

    cudaFuncSetAttribute(hgemm3<QKVD, true, true, false>,
                         cudaFuncAttributeMaxDynamicSharedMemorySize, HG_SMEM);
    cudaFuncSetAttribute(hgemm3<DIMC, false, false, true>,
                         cudaFuncAttributeMaxDynamicSharedMemorySize, HG_SMEM);

    // prep: weight splits + bias materialization
    conv_w<<<(192 * QKVD + 255) / 256, 256>>>(w_qkv, (__half*)wqh, (__half*)wql,
                                              192 * QKVD);
    conv_w<<<(192 * DIMC + 255) / 256, 256>>>(w_proj, (__half*)wph, (__half*)wpl,
                                              192 * DIMC);
    bias_pre<<<384, 256>>>(bias_table);

    // 1) QKV projection
    hgemm3<QKVD, true, true, false><<<MROWS / 128, 256, HG_SMEM>>>(
        x, (const __half*)wqh, (const __half*)wql, nullptr, qkv_ptr);

    // 2) windowed attention
    attn_kernel<<<dim3(WN, HEADS), 288>>>(mask);

    // 3) output projection
    hgemm3<DIMC, false, false, true><<<MROWS / 128, 256, HG_SMEM>>>(
        (const float*)att_ptr, (const __half*)wph, (const __half*)wpl,
        b_proj, out);
}

// round 10
// speedup vs baseline: 3.1460x; 1.2268x over previous
#include <cuda_runtime.h>
#include <cuda_fp16.h>
#include <cstdint>
#include <stdint.h>

// ---------------------------------------------------------------------------
// EarthAttention3D — mma.sync f16, occupancy-tuned (R8)
// ---------------------------------------------------------------------------

#define WN      960
#define PT      144
#define DIMC    192
#define HEADS   6
#define DH      32
#define QKVD    576
#define MROWS   (WN * PT)          // 138240
#define QSCALEV 0.17677669529663687f

__device__ __half g_qkvh[(size_t)MROWS * QKVD];   // 159 MB
__device__ __half g_atth[(size_t)MROWS * DIMC];   // 53 MB
__device__ __half g_bias[(size_t)384 * PT * PT];  // 15.9 MB (L2-resident)
__device__ __half g_wqhi[192 * QKVD], g_wqlo[192 * QKVD];
__device__ __half g_wphi[192 * DIMC], g_wplo[192 * DIMC];

// ---------------------------------------------------------------------------
__device__ __forceinline__ void mma16816(float d[4], const unsigned a[4],
                                         const unsigned b0, const unsigned b1)
{
    asm volatile(
        "mma.sync.aligned.m16n8k16.row.col.f32.f16.f16.f32 "
        "{%0,%1,%2,%3}, {%4,%5,%6,%7}, {%8,%9}, {%0,%1,%2,%3};\n"
        : "+f"(d[0]), "+f"(d[1]), "+f"(d[2]), "+f"(d[3])
        : "r"(a[0]), "r"(a[1]), "r"(a[2]), "r"(a[3]), "r"(b0), "r"(b1));
}
__device__ __forceinline__ void ldmx4(unsigned r[4], unsigned addr)
{
    asm volatile("ldmatrix.sync.aligned.m8n8.x4.shared.b16 {%0,%1,%2,%3}, [%4];"
                 : "=r"(r[0]), "=r"(r[1]), "=r"(r[2]), "=r"(r[3]) : "r"(addr));
}
__device__ __forceinline__ void ldmx4t(unsigned r[4], unsigned addr)
{
    asm volatile("ldmatrix.sync.aligned.m8n8.x4.trans.shared.b16 {%0,%1,%2,%3}, [%4];"
                 : "=r"(r[0]), "=r"(r[1]), "=r"(r[2]), "=r"(r[3]) : "r"(addr));
}
__device__ __forceinline__ void cpa16(unsigned s, const void* g)
{
    asm volatile("cp.async.ca.shared.global [%0], [%1], 16;\n" :: "r"(s), "l"(g));
}
__device__ __forceinline__ void cp_commit()
{
    asm volatile("cp.async.commit_group;\n");
}
template<int I> __device__ __forceinline__ void cp_wait()
{
    asm volatile("cp.async.wait_group %0;\n" :: "n"(I));
}

// FFMA-only exp
__device__ __forceinline__ float fexp(float x)
{
    float t = x * 1.4426950408889634f;
    float n = rintf(t);
    float f = t - n;
    float p = 1.33333642e-3f;
    p = fmaf(p, f, 9.61812910e-3f);
    p = fmaf(p, f, 5.55041087e-2f);
    p = fmaf(p, f, 2.40226507e-1f);
    p = fmaf(p, f, 6.93147181e-1f);
    p = fmaf(p, f, 1.0f);
    int e = (int)n;
    e = max(e, -120);
    return __int_as_float((e + 127) << 23) * p;
}

// ---------------------------------------------------------------------------
__global__ void conv_w(const float* __restrict__ w, __half* __restrict__ hi,
                       __half* __restrict__ lo, int n)
{
    int i = blockIdx.x * 256 + threadIdx.x;
    if (i < n) {
        float v = w[i];
        __half h = __float2half_rn(v);
        hi[i] = h;
        lo[i] = __float2half_rn(v - __half2float(h));
    }
}

// ---------------------------------------------------------------------------
// hgemm3: C[M,N] = A[M,192] * B[192,N]
//   A_HALF=0: A fp32, 3-term split (hi*hi + lo*hi + hi*lo)
//   A_HALF=1: A half (exact), 2-term (A*hi + A*lo)
// Block = 64 rows x full N (chunks of 64), 8 warps (4m x 2n), 3 CTAs/SM.
// ---------------------------------------------------------------------------
#define AST 200                     // A smem stride (halves)
#define BST 72                      // B smem stride (halves)
#define SMEM_QKV ((2 * 64 * AST + 2 * 2 * 32 * BST) * 2)   // 69,632 B
#define SMEM_PRJ ((    64 * AST + 2 * 2 * 32 * BST) * 2)   // 44,032 B

template<int N, bool A_HALF, bool OUT_HALF, bool QSCALE, bool ADDB>
__global__ __launch_bounds__(256, 3)
void hgemm3(const void* __restrict__ Ain, const __half* __restrict__ Bhi,
            const __half* __restrict__ Blo, const float* __restrict__ bias,
            void* __restrict__ Cout)
{
    extern __shared__ __half sm[];
    __half* Ahi = sm;                                      // [64][AST]
    __half* Alo = Ahi + 64 * AST;                          // (A_HALF: unused)
    __half* Bbuf = Ahi + (A_HALF ? 64 * AST : 2 * 64 * AST);

    const int tid  = threadIdx.x;
    const int warp = tid >> 5, lane = tid & 31;
    const int wm = warp >> 1, wn = warp & 1;
    const int g  = lane >> 2, c2 = (lane & 3) * 2;
    const int laneRow = lane & 15, laneCol = (lane >> 4) * 8;
    const int rowBlk = blockIdx.x * 64;

    const unsigned aHiAddr = (unsigned)__cvta_generic_to_shared(Ahi);
    const unsigned aLoOff  = 64 * AST * 2;                 // bytes
    const unsigned bAddr   = (unsigned)__cvta_generic_to_shared(Bbuf);

    // ---- stage A (64 x 192) once ----------------------------------------
    if (A_HALF) {
        const __half* Ah = (const __half*)Ain;
        for (int idx = tid; idx < 64 * 24; idx += 256) {
            const int row = idx / 24, g8 = (idx % 24) * 8;
            *(uint4*)&Ahi[row * AST + g8] =
                *(const uint4*)&Ah[(size_t)(rowBlk + row) * 192 + g8];
        }
    } else {
        const float* Af = (const float*)Ain;
        for (int idx = tid; idx < 64 * 48; idx += 256) {
            const int row = idx / 48, f4 = idx % 48;
            float4 v = *(const float4*)&Af[(size_t)(rowBlk + row) * 192 + f4 * 4];
            float va[4] = {v.x, v.y, v.z, v.w};
            __half hh[4], hl[4];
            #pragma unroll
            for (int i = 0; i < 4; i++) {
                hh[i] = __float2half_rn(va[i]);
                hl[i] = __float2half_rn(va[i] - __half2float(hh[i]));
            }
            *(uint2*)&Ahi[row * AST + f4 * 4] = *(uint2*)hh;
            *(uint2*)&Alo[row * AST + f4 * 4] = *(uint2*)hl;
        }
    }

    const int br = tid >> 3, bseg = (tid & 7) * 8;   // 32 rows x 8x8 halves

    #pragma unroll 1
    for (int c0 = 0; c0 < N; c0 += 64) {
        {   // prologue: stage 0 <- k0=0
            unsigned s = bAddr + (unsigned)(br * BST + bseg) * 2;
            cpa16(s,                  &Bhi[(size_t)br * N + c0 + bseg]);
            cpa16(s + 32 * BST * 2,   &Blo[(size_t)br * N + c0 + bseg]);
            cp_commit();
        }

        float acc[4][4] = {};

        #pragma unroll
        for (int ks = 0; ks < 6; ks++) {
            if (ks < 5) {
                const int kn = (ks + 1) * 32;
                unsigned s = bAddr + (unsigned)(((ks + 1) & 1) * 64 * BST
                                                + br * BST + bseg) * 2;
                cpa16(s,                &Bhi[(size_t)(kn + br) * N + c0 + bseg]);
                cpa16(s + 32 * BST * 2, &Blo[(size_t)(kn + br) * N + c0 + bseg]);
                cp_commit();
                cp_wait<1>();
            } else {
                cp_wait<0>();
            }
            __syncthreads();

            const int k0 = ks * 32;
            const unsigned bStage = bAddr + (unsigned)((ks & 1) * 64 * BST) * 2;

            unsigned ah[2][4], al[2][4];
            #pragma unroll
            for (int t = 0; t < 2; t++) {
                unsigned ad = aHiAddr +
                    (unsigned)((wm * 16 + laneRow) * AST
                               + k0 + t * 16 + laneCol) * 2;
                ldmx4(ah[t], ad);
                if (!A_HALF) ldmx4(al[t], ad + aLoOff);
            }
            unsigned bh[2][2][4], bl[2][2][4];
            #pragma unroll
            for (int t = 0; t < 2; t++)
                #pragma unroll
                for (int p = 0; p < 2; p++) {
                    unsigned bd = bStage +
                        (unsigned)((t * 16 + laneRow) * BST
                                   + wn * 32 + p * 16 + laneCol) * 2;
                    ldmx4t(bh[t][p], bd);
                    ldmx4t(bl[t][p], bd + 32 * BST * 2);
                }
            #pragma unroll
            for (int t = 0; t < 2; t++)
                #pragma unroll
                for (int p = 0; p < 2; p++) {
                    if (A_HALF) {
                        mma16816(acc[2*p  ], ah[t], bh[t][p][0], bh[t][p][1]);
                        mma16816(acc[2*p  ], ah[t], bl[t][p][0], bl[t][p][1]);
                        mma16816(acc[2*p+1], ah[t], bh[t][p][2], bh[t][p][3]);
                        mma16816(acc[2*p+1], ah[t], bl[t][p][2], bl[t][p][3]);
                    } else {
                        mma16816(acc[2*p  ], ah[t], bh[t][p][0], bh[t][p][1]);
                        mma16816(acc[2*p  ], al[t], bh[t][p][0], bh[t][p][1]);
                        mma16816(acc[2*p  ], ah[t], bl[t][p][0], bl[t][p][1]);
                        mma16816(acc[2*p+1], ah[t], bh[t][p][2], bh[t][p][3]);
                        mma16816(acc[2*p+1], al[t], bh[t][p][2], bh[t][p][3]);
                        mma16816(acc[2*p+1], ah[t], bl[t][p][2], bl[t][p][3]);
                    }
                }
            __syncthreads();
        }

        // ---- epilogue for this 64-col chunk -----------------------------
        const int row0 = rowBlk + wm * 16 + g;
        #pragma unroll
        for (int n = 0; n < 4; n++) {
            const int col = c0 + wn * 32 + n * 8 + c2;
            if (OUT_HALF) {
                const float s = (QSCALE && col < DIMC) ? QSCALEV : 1.0f;
                __half* o = (__half*)Cout;
                __half2 h0 = __floats2half2_rn(acc[n][0] * s, acc[n][1] * s);
                __half2 h1 = __floats2half2_rn(acc[n][2] * s, acc[n][3] * s);
                *(__half2*)&o[(size_t)row0 * N + col]       = h0;
                *(__half2*)&o[(size_t)(row0 + 8) * N + col] = h1;
            } else {
                float bx = 0.f, by = 0.f;
                if (ADDB) { float2 bv = *(const float2*)&bias[col]; bx = bv.x; by = bv.y; }
                float* o = (float*)Cout;
                *(float2*)&o[(size_t)row0 * N + col] =
                    make_float2(acc[n][0] + bx, acc[n][1] + by);
                *(float2*)&o[(size_t)(row0 + 8) * N + col] =
                    make_float2(acc[n][2] + bx, acc[n][3] + by);
            }
        }
    }
}

// ---------------------------------------------------------------------------
// earth-bias materialization
// ---------------------------------------------------------------------------
__global__ __launch_bounds__(256)
void bias_pre(const float* __restrict__ table)
{
    const int wh = blockIdx.x;                    // wt*6 + h
    __half* out = g_bias + (size_t)wh * PT * PT;
    for (int t = threadIdx.x; t < PT * PT; t += 256) {
        const int i = t / PT, j = t % PT;
        const int zi = i / 72, hi = (i % 72) / 12, wi = i % 12;
        const int zj = j / 72, hj = (j % 72) / 12, wj = j % 12;
        const int idx = (zi + 2 * zj) * 828 + (hi + 6 * hj) * 23 + (wi - wj + 11);
        out[t] = __float2half_rn(__ldg(&table[(size_t)idx * 384 + wh]));
    }
}

// ---------------------------------------------------------------------------
// Attention: block per (w,h); 9 warps, warp = 16-row strip.
// S packed half2 in regs; deferred softmax normalization; half output.
// ---------------------------------------------------------------------------
__global__ __launch_bounds__(288, 2)
void attn_kernel(const float* __restrict__ mask)
{
    __shared__ __half Qh[PT][40], Kh[PT][40];
    __shared__ __half Vt[DH][152];

    const int w = blockIdx.x, h = blockIdx.y;
    const int tid = threadIdx.x;
    const int warp = tid >> 5, lane = tid & 31;
    const int g = lane >> 2, c2 = (lane & 3) * 2;

    const __half* qkv = g_qkvh + (size_t)w * PT * QKVD + h * DH;
    for (int t = tid; t < 3 * 576; t += 288) {
        const int sel = t / 576, r = t % 576;
        const int p = r >> 2, grp = (r & 3) * 8;
        uint4 v = *(const uint4*)&qkv[(size_t)p * QKVD + sel * DIMC + grp];
        if (sel == 0)      *(uint4*)&Qh[p][grp] = v;
        else if (sel == 1) *(uint4*)&Kh[p][grp] = v;
        else {
            const __half* hv = (const __half*)&v;
            #pragma unroll
            for (int i = 0; i < 8; i++) Vt[grp + i][p] = hv[i];
        }
    }
    __syncthreads();

    const int mrow = warp * 16;
    unsigned aq[2][4];
    #pragma unroll
    for (int ks = 0; ks < 2; ks++) {
        const int k0 = ks * 16;
        aq[ks][0] = *(const unsigned*)&Qh[mrow + g    ][k0 + c2    ];
        aq[ks][1] = *(const unsigned*)&Qh[mrow + g + 8][k0 + c2    ];
        aq[ks][2] = *(const unsigned*)&Qh[mrow + g    ][k0 + c2 + 8];
        aq[ks][3] = *(const unsigned*)&Qh[mrow + g + 8][k0 + c2 + 8];
    }

    const int r0 = mrow + g, r1 = r0 + 8;
    const __half* bb = g_bias + (size_t)((w / 15) * HEADS + h) * PT * PT;
    const float*  mm = mask + (size_t)w * PT * PT;

    // ---- pass 1: S = QK^T + bias + mask, packed half2, track max --------
    unsigned Sl[18], Sh[18];          // rows r0 / r1, packed pairs
    float mx0 = -1e30f, mx1 = -1e30f;
    #pragma unroll
    for (int j = 0; j < 18; j++) {
        float a4[4] = {0.f, 0.f, 0.f, 0.f};
        unsigned b0 = *(const unsigned*)&Kh[j * 8 + g][c2    ];
        unsigned b1 = *(const unsigned*)&Kh[j * 8 + g][c2 + 8];
        mma16816(a4, aq[0], b0, b1);
        b0 = *(const unsigned*)&Kh[j * 8 + g][16 + c2    ];
        b1 = *(const unsigned*)&Kh[j * 8 + g][16 + c2 + 8];
        mma16816(a4, aq[1], b0, b1);

        const int col = j * 8 + c2;
        const __half2 bv0 = *(const __half2*)&bb[r0 * PT + col];
        const __half2 bv1 = *(const __half2*)&bb[r1 * PT + col];
        const float2  m0 = *(const float2*)&mm[r0 * PT + col];
        const float2  m1 = *(const float2*)&mm[r1 * PT + col];
        a4[0] += __low2float(bv0)  + m0.x;
        a4[1] += __high2float(bv0) + m0.y;
        a4[2] += __low2float(bv1)  + m1.x;
        a4[3] += __high2float(bv1) + m1.y;

        mx0 = fmaxf(mx0, fmaxf(a4[0], a4[1]));
        mx1 = fmaxf(mx1, fmaxf(a4[2], a4[3]));
        __half2 h0 = __floats2half2_rn(a4[0], a4[1]);
        __half2 h1 = __floats2half2_rn(a4[2], a4[3]);
        Sl[j] = *(unsigned*)&h0;
        Sh[j] = *(unsigned*)&h1;
    }
    #pragma unroll
    for (int off = 1; off <= 2; off <<= 1) {
        mx0 = fmaxf(mx0, __shfl_xor_sync(0xffffffffu, mx0, off));
        mx1 = fmaxf(mx1, __shfl_xor_sync(0xffffffffu, mx1, off));
    }

    // ---- pass 2: exp (unnormalized), sum --------------------------------
    float s0 = 0.f, s1 = 0.f;
    #pragma unroll
    for (int j = 0; j < 18; j++) {
        __half2 v0 = *(__half2*)&Sl[j];
        __half2 v1 = *(__half2*)&Sh[j];
        float e0 = fexp(__low2float(v0) - mx0);
        float e1 = fexp(__high2float(v0) - mx0);
        float e2 = fexp(__low2float(v1) - mx1);
        float e3 = fexp(__high2float(v1) - mx1);
        s0 += e0 + e1;  s1 += e2 + e3;
        __half2 h0 = __floats2half2_rn(e0, e1);
        __half2 h1 = __floats2half2_rn(e2, e3);
        Sl[j] = *(unsigned*)&h0;
        Sh[j] = *(unsigned*)&h1;
    }
    #pragma unroll
    for (int off = 1; off <= 2; off <<= 1) {
        s0 += __shfl_xor_sync(0xffffffffu, s0, off);
        s1 += __shfl_xor_sync(0xffffffffu, s1, off);
    }
    const float i0 = 1.f / s0, i1 = 1.f / s1;

    // ---- O = P V (unnormalized), scale at epilogue ----------------------
    float O[4][4] = {};
    #pragma unroll
    for (int t = 0; t < 9; t++) {
        const unsigned a[4] = {Sl[2 * t], Sh[2 * t], Sl[2 * t + 1], Sh[2 * t + 1]};
        #pragma unroll
        for (int n = 0; n < 4; n++) {
            unsigned b0 = *(const unsigned*)&Vt[n * 8 + g][t * 16 + c2    ];
            unsigned b1 = *(const unsigned*)&Vt[n * 8 + g][t * 16 + c2 + 8];
            mma16816(O[n], a, b0, b1);
        }
    }
    __half* op = g_atth + (size_t)w * PT * DIMC + h * DH;
    #pragma unroll
    for (int n = 0; n < 4; n++) {
        const int col = n * 8 + c2;
        __half2 h0 = __floats2half2_rn(O[n][0] * i0, O[n][1] * i0);
        __half2 h1 = __floats2half2_rn(O[n][2] * i1, O[n][3] * i1);
        *(__half2*)&op[(size_t)r0 * DIMC + col] = h0;
        *(__half2*)&op[(size_t)r1 * DIMC + col] = h1;
    }
}

// ---------------------------------------------------------------------------
extern "C" void kernel_launch(void* const* d_in, const int* in_sizes, int n_in,
                              void* d_out, int out_size)
{
    const float* x          = (const float*)d_in[0];
    const float* mask       = (const float*)d_in[1];
    const float* w_qkv      = (const float*)d_in[2];
    const float* w_proj     = (const float*)d_in[3];
    const float* b_proj     = (const float*)d_in[4];
    const float* bias_table = (const float*)d_in[5];
    float* out = (float*)d_out;

    void *qkv_ptr = nullptr, *att_ptr = nullptr;
    void *wqh = nullptr, *wql = nullptr, *wph = nullptr, *wpl = nullptr;
    cudaGetSymbolAddress(&qkv_ptr, g_qkvh);
    cudaGetSymbolAddress(&att_ptr, g_atth);
    cudaGetSymbolAddress(&wqh, g_wqhi);
    cudaGetSymbolAddress(&wql, g_wqlo);
    cudaGetSymbolAddress(&wph, g_wphi);
    cudaGetSymbolAddress(&wpl, g_wplo);

    cudaFuncSetAttribute(hgemm3<QKVD, false, true, true, false>,
                         cudaFuncAttributeMaxDynamicSharedMemorySize, SMEM_QKV);
    cudaFuncSetAttribute(hgemm3<DIMC, true, false, false, true>,
                         cudaFuncAttributeMaxDynamicSharedMemorySize, SMEM_PRJ);

    // prep: weight splits + bias materialization
    conv_w<<<(192 * QKVD + 255) / 256, 256>>>(w_qkv, (__half*)wqh, (__half*)wql,
                                              192 * QKVD);
    conv_w<<<(192 * DIMC + 255) / 256, 256>>>(w_proj, (__half*)wph, (__half*)wpl,
                                              192 * DIMC);
    bias_pre<<<384, 256>>>(bias_table);

    // 1) QKV projection (fp32 A, 3-term)
    hgemm3<QKVD, false, true, true, false><<<MROWS / 64, 256, SMEM_QKV>>>(
        x, (const __half*)wqh, (const __half*)wql, nullptr, qkv_ptr);

    // 2) windowed attention
    attn_kernel<<<dim3(WN, HEADS), 288>>>(mask);

    // 3) output projection (half A, 2-term, fp32 out + bias)
    hgemm3<DIMC, true, false, false, true><<<MROWS / 64, 256, SMEM_PRJ>>>(
        att_ptr, (const __half*)wph, (const __half*)wpl, b_proj, out);
}